// round 5
// baseline (speedup 1.0000x reference)
#include <cuda_runtime.h>
#include <cuda_bf16.h>

// Grouped submanifold sparse conv, N=400000, C_IN=C_OUT=64, GROUPS=4, K=27.
// R5: occupancy round. Each CTA handles 2 of the 4 groups (32 channels) for
// its voxel range: smem 55.4KB, ~60 regs -> 4 CTAs/SM = 32 warps (2x R1-R4).
// Lane = (local_group, co): one output channel per lane; w[16] scalar regs,
// acc 8 regs. Weight amortization kept: 8 voxels/warp, weights reloaded only
// per union-offset (16 x LDS.32 = 1 wavefront, groups bank-disjoint via pad).

#define KOFF   27
#define WK     256                  // floats per (g,k): 16ci x 16co
#define WGRP   (KOFF * WK)          // 6912 floats per group
#define PADG   (WGRP + 16)          // 16-float pad: 16-bank shift for group 1
#define SMEM_BYTES (2 * PADG * 4)   // 55,424 B
#define VPW 8
#define FULL 0xffffffffu

__global__ __launch_bounds__(256, 4)
void subm_conv_r5(const float* __restrict__ feat,
                  const float* __restrict__ weight,
                  const float* __restrict__ bias,
                  const int* __restrict__ nb,
                  float* __restrict__ out,
                  int N, int iters_per_warp, int total_iters)
{
    extern __shared__ float sw[];
    const int h = blockIdx.x & 1;            // group-pair half: groups {2h, 2h+1}

    // Stage this half's weights: sw[g'][k][ci][co], g' in {0,1}
    const float* wsrc = weight + (size_t)h * 2 * WGRP;
    for (int i = threadIdx.x; i < 2 * WGRP; i += 256) {
        int gl = i / WGRP;
        sw[gl * PADG + (i - gl * WGRP)] = wsrc[i];
    }
    __syncthreads();

    const int lane = threadIdx.x & 31;
    const int gp   = lane >> 4;              // local group 0/1
    const int co   = lane & 15;              // output channel within group
    const float bz = bias[h * 32 + lane];
    const float* swb = sw + gp * PADG + co;  // + k*256 + ci*16
    const int f4ofs = (h * 2 + gp) * 4;      // float4 offset of group slice

    const int warp_in_half = (int)(blockIdx.x >> 1) * 8 + (int)(threadIdx.x >> 5);
    int it0 = warp_in_half * iters_per_warp;
    int it1 = it0 + iters_per_warp;
    if (it1 > total_iters) it1 = total_iters;

    for (int it = it0; it < it1; ++it) {
        const int vb = it * VPW;
        const int* nbrow = nb + (size_t)vb * KOFF;

        // Activity byte: bit j = voxel vb+j active at offset 'lane' (<27).
        unsigned am = 0;
        #pragma unroll
        for (int j = 0; j < VPW; ++j) {
            int v = vb + j;
            int id = (lane < KOFF && v < N) ? nbrow[j * KOFF + lane] : -1;
            am |= (id >= 0 ? 1u : 0u) << j;
        }
        unsigned uni = __ballot_sync(FULL, am != 0);

        float a0 = bz, a1 = bz, a2 = bz, a3 = bz;
        float a4 = bz, a5 = bz, a6 = bz, a7 = bz;

        while (uni) {
            const int k = __ffs(uni) - 1;
            uni &= uni - 1;
            const unsigned jm = __shfl_sync(FULL, am, k);

            // One weight column for this k: w[ci], 16 x LDS.32, 1 wavefront.
            const float* wk = swb + k * WK;
            float w0  = wk[0 * 16],  w1  = wk[1 * 16],  w2  = wk[2 * 16],  w3  = wk[3 * 16];
            float w4  = wk[4 * 16],  w5  = wk[5 * 16],  w6  = wk[6 * 16],  w7  = wk[7 * 16];
            float w8  = wk[8 * 16],  w9  = wk[9 * 16],  w10 = wk[10 * 16], w11 = wk[11 * 16];
            float w12 = wk[12 * 16], w13 = wk[13 * 16], w14 = wk[14 * 16], w15 = wk[15 * 16];

            const int* nk = nbrow + k;

            #pragma unroll
            for (int j = 0; j < VPW; ++j) {
                if ((jm >> j) & 1u) {            // warp-uniform branch
                    const int ni = nk[j * KOFF]; // uniform LDG, L1-hot row
                    const float4* fp = (const float4*)feat + (size_t)ni * 16 + f4ofs;
                    float4 fa = fp[0], fb = fp[1], fc = fp[2], fd = fp[3];
                    // two FFMA chains, merged at the end
                    float x  = fa.x * w0;   float y  = fa.y * w1;
                    x += fa.z * w2;         y += fa.w * w3;
                    x += fb.x * w4;         y += fb.y * w5;
                    x += fb.z * w6;         y += fb.w * w7;
                    x += fc.x * w8;         y += fc.y * w9;
                    x += fc.z * w10;        y += fc.w * w11;
                    x += fd.x * w12;        y += fd.y * w13;
                    x += fd.z * w14;        y += fd.w * w15;
                    x += y;
                    switch (j) {                 // static j via unroll: folds away
                        case 0: a0 += x; break;
                        case 1: a1 += x; break;
                        case 2: a2 += x; break;
                        case 3: a3 += x; break;
                        case 4: a4 += x; break;
                        case 5: a5 += x; break;
                        case 6: a6 += x; break;
                        default: a7 += x; break;
                    }
                }
            }
        }

        // Store: 32 contiguous floats per voxel at channel offset h*32.
        float* ob = out + (size_t)vb * 64 + h * 32 + lane;
        if (vb + 7 < N) {
            ob[0 * 64] = a0; ob[1 * 64] = a1; ob[2 * 64] = a2; ob[3 * 64] = a3;
            ob[4 * 64] = a4; ob[5 * 64] = a5; ob[6 * 64] = a6; ob[7 * 64] = a7;
        } else {
            if (vb + 0 < N) ob[0 * 64] = a0;
            if (vb + 1 < N) ob[1 * 64] = a1;
            if (vb + 2 < N) ob[2 * 64] = a2;
            if (vb + 3 < N) ob[3 * 64] = a3;
            if (vb + 4 < N) ob[4 * 64] = a4;
            if (vb + 5 < N) ob[5 * 64] = a5;
            if (vb + 6 < N) ob[6 * 64] = a6;
            if (vb + 7 < N) ob[7 * 64] = a7;
        }
    }
}

extern "C" void kernel_launch(void* const* d_in, const int* in_sizes, int n_in,
                              void* d_out, int out_size)
{
    const float* feat   = (const float*)d_in[0];  // [N, 64]
    const float* weight = (const float*)d_in[1];  // [4, 27, 16, 16]
    const float* bias   = (const float*)d_in[2];  // [64]
    const int*   nb     = (const int*)d_in[3];    // [N, 27]
    float* out = (float*)d_out;

    int N = in_sizes[0] / 64;

    // Idempotent, enqueues no work; safe under graph capture.
    cudaFuncSetAttribute(subm_conv_r5,
                         cudaFuncAttributeMaxDynamicSharedMemorySize, SMEM_BYTES);

    const int blocks = 608;             // 4 CTAs/SM x 152 SMs; bid&1 = group half
    const int threads = 256;
    const int warps_per_half = (blocks / 2) * (threads / 32);
    int total_iters = (N + VPW - 1) / VPW;
    int iters_per_warp = (total_iters + warps_per_half - 1) / warps_per_half;

    subm_conv_r5<<<blocks, threads, SMEM_BYTES>>>(feat, weight, bias, nb,
                                                  out, N, iters_per_warp,
                                                  total_iters);
    (void)n_in; (void)out_size;
}

// round 6
// speedup vs baseline: 1.3876x; 1.3876x over previous
#include <cuda_runtime.h>
#include <cstdint>

// Grouped submanifold sparse conv, N=400000, C_IN=C_OUT=64, GROUPS=4, K=27.
// R6: latency round. Evidence R1-R5: no pipe saturated, DRAM bytes constant,
// ILP/occupancy changes neutral => exposed gather latency with MLP~2/warp.
// Fix: cp.async (LDGSTS, zero register cost) stages gathered 256B feature
// rows into per-warp smem slots, 2 waves x 12 bodies deep => ~24 independent
// fetches in flight per warp. Compute consumes staged rows wave-by-wave.
// Weights register-cached per union-offset (VPW=16 => ~3.7x reuse).

#define KOFF 27
#define WK   256                    // floats per (g,k)
#define WGRP (KOFF * WK)            // 6912
#define PG   (WGRP + 16)            // padded group stride (optimal deg-2 banks)
#define W_FLOATS (4 * PG)           // 27712
#define W_BYTES  (W_FLOATS * 4)     // 110848
#define VPW  16
#define WAVE 12                     // bodies per async wave
#define NSLOT (2 * WAVE)            // staging slots per warp (256 B each)
#define NWARPS 16
#define SMEM_BYTES (W_BYTES + NWARPS * NSLOT * 256)   // 209152
#define FULL 0xffffffffu

#define CP_ASYNC16(dst, src) \
    asm volatile("cp.async.cg.shared.global [%0], [%1], 16;" \
                 :: "r"(dst), "l"(src) : "memory")
#define CP_COMMIT() asm volatile("cp.async.commit_group;" ::: "memory")
#define CP_WAIT1()  asm volatile("cp.async.wait_group 1;" ::: "memory")

__global__ __launch_bounds__(512, 1)
void subm_conv_r6(const float* __restrict__ feat,
                  const float* __restrict__ weight,
                  const float* __restrict__ bias,
                  const int* __restrict__ nb,
                  float* __restrict__ out,
                  int N, int total_iters, int totwarps)
{
    extern __shared__ float sw[];
    for (int i = threadIdx.x; i < 4 * WGRP; i += 512) {
        int g = i / WGRP;
        sw[g * PG + (i - g * WGRP)] = weight[i];
    }
    __syncthreads();

    const int lane = threadIdx.x & 31;
    const int wid  = threadIdx.x >> 5;
    float* stagef = sw + W_FLOATS + wid * (NSLOT * 64);
    const uint32_t stage_u32 = (uint32_t)__cvta_generic_to_shared(stagef);

    const int g   = lane >> 3;           // group of this lane
    const int co0 = (lane & 7) * 2;      // out-channel pair within group
    const float bx = bias[2 * lane];
    const float by = bias[2 * lane + 1];
    const float* wgbase = sw + g * PG + co0;

    const int gwarp = blockIdx.x * NWARPS + wid;

    for (int it = gwarp; it < total_iters; it += totwarps) {
        const int vb = it * VPW;
        const int* nbrow = nb + (size_t)vb * KOFF;

        // Activity mask: bit j of am (lane k<27) = voxel vb+j active at k.
        unsigned am = 0;
        #pragma unroll
        for (int j = 0; j < VPW; ++j) {
            int v = vb + j;
            int id = (lane < KOFF && v < N) ? nbrow[j * KOFF + lane] : -1;
            am |= (id >= 0 ? 1u : 0u) << j;
        }
        const unsigned uni = __ballot_sync(FULL, am != 0);

        // Fill / compute cursors over the identical warp-uniform body stream.
        unsigned fU = uni, fJ = 0; int fK = 0;
        unsigned cU = uni, cJ = 0; int cK = 0;

        auto fnext = [&](int& j, int& k) -> bool {
            if (fJ == 0) {
                if (fU == 0) return false;
                fK = __ffs(fU) - 1; fU &= fU - 1;
                fJ = __shfl_sync(FULL, am, fK);
            }
            j = __ffs(fJ) - 1; fJ &= fJ - 1; k = fK; return true;
        };
        auto cnext = [&](int& j, int& k) -> bool {
            if (cJ == 0) {
                if (cU == 0) return false;
                cK = __ffs(cU) - 1; cU &= cU - 1;
                cJ = __shfl_sync(FULL, am, cK);
            }
            j = __ffs(cJ) - 1; cJ &= cJ - 1; k = cK; return true;
        };

        // Fill one wave: up to WAVE bodies, 2 bodies per cp.async instruction
        // (lanes 0-15 copy body1's 256B row, lanes 16-31 body2's).
        auto fill_wave = [&](int slotbase) -> int {
            int n = 0;
            while (n < WAVE) {
                int j1, k1, j2, k2;
                if (!fnext(j1, k1)) break;
                int ni1 = nbrow[j1 * KOFF + k1];       // uniform, L1-hot row
                bool has2 = fnext(j2, k2);
                int ni2 = has2 ? nbrow[j2 * KOFF + k2] : ni1;
                int ni = (lane < 16) ? ni1 : ni2;
                uint32_t dst = stage_u32
                             + (uint32_t)(slotbase + n + (lane >> 4)) * 256u
                             + (uint32_t)(lane & 15) * 16u;
                const float* src = feat + (size_t)ni * 64 + (lane & 15) * 4;
                if (lane < 16 || has2) CP_ASYNC16(dst, src);
                n += has2 ? 2 : 1;
            }
            CP_COMMIT();
            return n;
        };

        float2 a0={bx,by},a1={bx,by},a2={bx,by},a3={bx,by};
        float2 a4={bx,by},a5={bx,by},a6={bx,by},a7={bx,by};
        float2 a8={bx,by},a9={bx,by},a10={bx,by},a11={bx,by};
        float2 a12={bx,by},a13={bx,by},a14={bx,by},a15={bx,by};

        float2 w[16];
        int kcur = -1;

        int cnt[3];
        cnt[0] = fill_wave(0);
        cnt[1] = fill_wave(WAVE);
        cnt[2] = 0;

        for (int i = 0; cnt[i % 3] > 0; ++i) {
            CP_WAIT1();            // wave i complete (<=1 group pending)
            __syncwarp();
            const int slotbase = (i & 1) * WAVE;
            const int ci = cnt[i % 3];
            for (int t = 0; t < ci; ++t) {
                int j, k;
                cnext(j, k);
                if (k != kcur) {   // reload weight column pair (~1 per 3.7 bodies)
                    kcur = k;
                    const float2* wp = (const float2*)(wgbase + k * WK);
                    #pragma unroll
                    for (int q = 0; q < 16; ++q) w[q] = wp[q * 8];
                }
                const float4* sp = (const float4*)(stagef + (slotbase + t) * 64 + g * 16);
                float4 fa = sp[0], fb = sp[1], fc = sp[2], fd = sp[3];
                // two interleaved FFMA chains
                float x = fa.x * w[0].x;   float xx = fa.y * w[1].x;
                float y = fa.x * w[0].y;   float yy = fa.y * w[1].y;
                x  += fa.z * w[2].x;   y  += fa.z * w[2].y;
                xx += fa.w * w[3].x;   yy += fa.w * w[3].y;
                x  += fb.x * w[4].x;   y  += fb.x * w[4].y;
                xx += fb.y * w[5].x;   yy += fb.y * w[5].y;
                x  += fb.z * w[6].x;   y  += fb.z * w[6].y;
                xx += fb.w * w[7].x;   yy += fb.w * w[7].y;
                x  += fc.x * w[8].x;   y  += fc.x * w[8].y;
                xx += fc.y * w[9].x;   yy += fc.y * w[9].y;
                x  += fc.z * w[10].x;  y  += fc.z * w[10].y;
                xx += fc.w * w[11].x;  yy += fc.w * w[11].y;
                x  += fd.x * w[12].x;  y  += fd.x * w[12].y;
                xx += fd.y * w[13].x;  yy += fd.y * w[13].y;
                x  += fd.z * w[14].x;  y  += fd.z * w[14].y;
                xx += fd.w * w[15].x;  yy += fd.w * w[15].y;
                x += xx; y += yy;
                switch (j) {       // warp-uniform
                    case 0:  a0.x += x;  a0.y += y;  break;
                    case 1:  a1.x += x;  a1.y += y;  break;
                    case 2:  a2.x += x;  a2.y += y;  break;
                    case 3:  a3.x += x;  a3.y += y;  break;
                    case 4:  a4.x += x;  a4.y += y;  break;
                    case 5:  a5.x += x;  a5.y += y;  break;
                    case 6:  a6.x += x;  a6.y += y;  break;
                    case 7:  a7.x += x;  a7.y += y;  break;
                    case 8:  a8.x += x;  a8.y += y;  break;
                    case 9:  a9.x += x;  a9.y += y;  break;
                    case 10: a10.x += x; a10.y += y; break;
                    case 11: a11.x += x; a11.y += y; break;
                    case 12: a12.x += x; a12.y += y; break;
                    case 13: a13.x += x; a13.y += y; break;
                    case 14: a14.x += x; a14.y += y; break;
                    default: a15.x += x; a15.y += y; break;
                }
            }
            cnt[(i + 2) % 3] = fill_wave(slotbase);  // refill freed slots
        }

        // Store 16 voxels x 64 channels (float2 per lane).
        float2* opb = (float2*)(out + (size_t)vb * 64);
        if (vb + VPW <= N) {
            opb[0*32+lane]=a0;   opb[1*32+lane]=a1;   opb[2*32+lane]=a2;   opb[3*32+lane]=a3;
            opb[4*32+lane]=a4;   opb[5*32+lane]=a5;   opb[6*32+lane]=a6;   opb[7*32+lane]=a7;
            opb[8*32+lane]=a8;   opb[9*32+lane]=a9;   opb[10*32+lane]=a10; opb[11*32+lane]=a11;
            opb[12*32+lane]=a12; opb[13*32+lane]=a13; opb[14*32+lane]=a14; opb[15*32+lane]=a15;
        } else {
            float2 aa[16] = {a0,a1,a2,a3,a4,a5,a6,a7,a8,a9,a10,a11,a12,a13,a14,a15};
            for (int j = 0; j < VPW; ++j)
                if (vb + j < N) opb[j*32+lane] = aa[j];
        }
    }
}

extern "C" void kernel_launch(void* const* d_in, const int* in_sizes, int n_in,
                              void* d_out, int out_size)
{
    const float* feat   = (const float*)d_in[0];  // [N, 64]
    const float* weight = (const float*)d_in[1];  // [4, 27, 16, 16]
    const float* bias   = (const float*)d_in[2];  // [64]
    const int*   nb     = (const int*)d_in[3];    // [N, 27]
    float* out = (float*)d_out;

    int N = in_sizes[0] / 64;

    // Idempotent, enqueues no work; safe under graph capture.
    cudaFuncSetAttribute(subm_conv_r6,
                         cudaFuncAttributeMaxDynamicSharedMemorySize, SMEM_BYTES);

    const int blocks = 152;              // 1 CTA/SM (206.8KB smem)
    const int threads = 512;             // 16 warps
    const int totwarps = blocks * (threads / 32);
    int total_iters = (N + VPW - 1) / VPW;

    subm_conv_r6<<<blocks, threads, SMEM_BYTES>>>(feat, weight, bias, nb,
                                                  out, N, total_iters, totwarps);
    (void)n_in; (void)out_size;
}

// round 7
// speedup vs baseline: 2.4312x; 1.7521x over previous
#include <cuda_runtime.h>
#include <cstdint>

// Grouped submanifold sparse conv, N=400000, C_IN=C_OUT=64, GROUPS=4, K=27.
// R7: body-list + smem-accumulator round. R6 evidence: cp.async fixed the
// stall structure (issue 31->46%) but per-body control machinery (16-way
// switch, dual ffs/shfl cursors) cost ~105 slots/body vs ~57 useful.
// Fix: per-batch prefix-scan enumerates all (voxel j, offset k, nbr ni)
// bodies into a packed smem list (k-major). Hot loop is then DENSE: uniform
// entry read, weight reload on k-change only, cp.async-staged features,
// accumulate via smem RMW (no switch, no per-body cursor).

#define KOFF 27
#define WK   256                        // floats per (g,k)
#define WGRP (KOFF * WK)                // 6912
#define PG   (WGRP + 16)                // 6928 padded group stride
#define W_FLOATS (4 * PG)               // 27712
#define VPW  8
#define NWARPS 16
#define ACC_F   W_FLOATS                           // acc area (float idx)
#define ACC_PER_WARP (VPW * 32 * 2)                // 512 floats = 2KB
#define RING_F  (ACC_F + NWARPS * ACC_PER_WARP)    // ring area
#define RING_PER_WARP 1024                         // 16 slots x 256B
#define LIST_F  (RING_F + NWARPS * RING_PER_WARP)
#define LIST_PER_WARP 224                          // max 216 entries
#define SMEM_FLOATS (LIST_F + NWARPS * LIST_PER_WARP)
#define SMEM_BYTES (SMEM_FLOATS * 4)               // 223488
#define FULL 0xffffffffu

#define CP_ASYNC16(dst, src) \
    asm volatile("cp.async.cg.shared.global [%0], [%1], 16;" \
                 :: "r"(dst), "l"(src) : "memory")
#define CP_COMMIT() asm volatile("cp.async.commit_group;" ::: "memory")
#define CP_WAIT1()  asm volatile("cp.async.wait_group 1;" ::: "memory")
#define CP_WAIT0()  asm volatile("cp.async.wait_group 0;" ::: "memory")

__global__ __launch_bounds__(512, 1)
void subm_conv_r7(const float* __restrict__ feat,
                  const float* __restrict__ weight,
                  const float* __restrict__ bias,
                  const int* __restrict__ nb,
                  float* __restrict__ out,
                  int N, int total_iters, int totwarps)
{
    extern __shared__ float sm[];
    for (int i = threadIdx.x; i < 4 * WGRP; i += 512) {
        int g = i / WGRP;
        sm[g * PG + (i - g * WGRP)] = weight[i];
    }
    __syncthreads();

    const int lane = threadIdx.x & 31;
    const int wid  = threadIdx.x >> 5;
    const int g    = lane >> 3;
    const int co0  = (lane & 7) * 2;
    const float bx = bias[2 * lane];
    const float by = bias[2 * lane + 1];
    const float* wgbase = sm + g * PG + co0;

    float2*   accw  = (float2*)(sm + ACC_F) + wid * (VPW * 32);
    float*    ringw = sm + RING_F + wid * RING_PER_WARP;
    uint32_t* lw    = (uint32_t*)(sm + LIST_F) + wid * LIST_PER_WARP;
    const uint32_t ring_u32 = (uint32_t)__cvta_generic_to_shared(ringw);

    for (int it = blockIdx.x * NWARPS + wid; it < total_iters; it += totwarps) {
        const int vb = it * VPW;
        const int* nbrow = nb + (size_t)vb * KOFF + lane;   // lane = offset k

        // ---- Phase A: build body list (k-major) via ballot-free scan ----
        unsigned am = 0;
        int idx[VPW];
        #pragma unroll
        for (int j = 0; j < VPW; ++j) {
            int v = vb + j;
            int id = (lane < KOFF && v < N) ? nbrow[j * KOFF] : -1;
            idx[j] = id;
            am |= (id >= 0 ? 1u : 0u) << j;
        }
        int pc = __popc(am);
        int s = pc;
        #pragma unroll
        for (int d = 1; d < 32; d <<= 1) {
            int t = __shfl_up_sync(FULL, s, d);
            if (lane >= d) s += t;
        }
        const int nb_total = __shfl_sync(FULL, s, 31);
        int pos = s - pc;                 // exclusive prefix
        unsigned em = am;
        while (em) {                      // emit this lane's bodies
            int j = __ffs(em) - 1; em &= em - 1;
            lw[pos++] = ((uint32_t)idx[j] << 8) | (uint32_t)(j << 5)
                      | (uint32_t)lane;
        }
        #pragma unroll
        for (int j = 0; j < VPW; ++j)     // acc init with bias
            accw[j * 32 + lane] = make_float2(bx, by);
        __syncwarp();

        // ---- async fill: wave of 8 bodies, 2 bodies per instruction ----
        auto fill = [&](int wbase, int slotbase) {
            #pragma unroll
            for (int p = 0; p < 8; p += 2) {
                int bi = wbase + p + (lane >> 4);
                if (bi < nb_total) {
                    uint32_t ni = lw[bi] >> 8;
                    uint32_t dst = ring_u32
                                 + (uint32_t)(slotbase + p + (lane >> 4)) * 256u
                                 + (uint32_t)(lane & 15) * 16u;
                    const float* src = feat + (size_t)ni * 64 + (lane & 15) * 4;
                    CP_ASYNC16(dst, src);
                }
            }
            CP_COMMIT();
        };

        fill(0, 0);
        fill(8, 8);

        // ---- Phase B: dense consume loop ----
        float2 w[16];
        int kcur = -1;
        for (int wbase = 0; wbase < nb_total; wbase += 8) {
            CP_WAIT1();
            __syncwarp();
            const int slotbase = ((wbase >> 3) & 1) * 8;
            const int cend = (wbase + 8 < nb_total) ? wbase + 8 : nb_total;
            for (int i = wbase; i < cend; ++i) {
                const uint32_t e = lw[i];             // warp-uniform entry
                const int k = (int)(e & 31u);
                const int j = (int)((e >> 5) & 7u);
                if (k != kcur) {                      // uniform, ~1 per 2.2 bodies
                    kcur = k;
                    const float2* wp = (const float2*)(wgbase + k * WK);
                    #pragma unroll
                    for (int q = 0; q < 16; ++q) w[q] = wp[q * 8];
                }
                const float4* sp = (const float4*)
                    (ringw + (slotbase + (i - wbase)) * 64 + g * 16);
                float4 fa = sp[0], fb = sp[1], fc = sp[2], fd = sp[3];
                // two interleaved FFMA chains
                float x  = fa.x * w[0].x;   float y  = fa.x * w[0].y;
                float xx = fa.y * w[1].x;   float yy = fa.y * w[1].y;
                x  += fa.z * w[2].x;   y  += fa.z * w[2].y;
                xx += fa.w * w[3].x;   yy += fa.w * w[3].y;
                x  += fb.x * w[4].x;   y  += fb.x * w[4].y;
                xx += fb.y * w[5].x;   yy += fb.y * w[5].y;
                x  += fb.z * w[6].x;   y  += fb.z * w[6].y;
                xx += fb.w * w[7].x;   yy += fb.w * w[7].y;
                x  += fc.x * w[8].x;   y  += fc.x * w[8].y;
                xx += fc.y * w[9].x;   yy += fc.y * w[9].y;
                x  += fc.z * w[10].x;  y  += fc.z * w[10].y;
                xx += fc.w * w[11].x;  yy += fc.w * w[11].y;
                x  += fd.x * w[12].x;  y  += fd.x * w[12].y;
                xx += fd.y * w[13].x;  yy += fd.y * w[13].y;
                x  += fd.z * w[14].x;  y  += fd.z * w[14].y;
                xx += fd.w * w[15].x;  yy += fd.w * w[15].y;
                x += xx; y += yy;
                float2* ap = accw + j * 32 + lane;    // smem RMW, no switch
                float2 a = *ap;
                a.x += x; a.y += y;
                *ap = a;
            }
            fill(wbase + 16, slotbase);               // refill freed wave
        }
        CP_WAIT0();
        __syncwarp();

        // ---- store 8 voxels x 64 channels ----
        #pragma unroll
        for (int j = 0; j < VPW; ++j) {
            int v = vb + j;
            if (v < N)
                ((float2*)(out + (size_t)v * 64))[lane] = accw[j * 32 + lane];
        }
        __syncwarp();
    }
}

extern "C" void kernel_launch(void* const* d_in, const int* in_sizes, int n_in,
                              void* d_out, int out_size)
{
    const float* feat   = (const float*)d_in[0];  // [N, 64]
    const float* weight = (const float*)d_in[1];  // [4, 27, 16, 16]
    const float* bias   = (const float*)d_in[2];  // [64]
    const int*   nb     = (const int*)d_in[3];    // [N, 27]
    float* out = (float*)d_out;

    int N = in_sizes[0] / 64;

    // Idempotent, enqueues no work; safe under graph capture.
    cudaFuncSetAttribute(subm_conv_r7,
                         cudaFuncAttributeMaxDynamicSharedMemorySize, SMEM_BYTES);

    const int blocks = 152;              // 1 CTA/SM (223.5KB smem)
    const int threads = 512;             // 16 warps
    const int totwarps = blocks * NWARPS;
    int total_iters = (N + VPW - 1) / VPW;

    subm_conv_r7<<<blocks, threads, SMEM_BYTES>>>(feat, weight, bias, nb,
                                                  out, N, total_iters, totwarps);
    (void)n_in; (void)out_size;
}